// round 15
// baseline (speedup 1.0000x reference)
#include <cuda_runtime.h>
#include <cuda_fp16.h>

#define NN 10000
#define EE 100000
#define EDGE_BLOCKS ((EE + 63) / 64)
#define W3H_BLOCKS (((NN + 31) / 32) * 16)
#define BIAS_BLOCKS ((NN + 63) / 64)

// ---------------- scratch (static device globals; no allocation) ----------------
__device__ float g_h[NN * 32];
__device__ float g_coord[NN * 3];
__device__ __align__(16) __half g_k2h[(size_t)EE * 128];
__device__ unsigned g_W3hB[(size_t)NN * 2048];   // [n][frag:64][lane:32] half2 words
__device__ __align__(8) unsigned g_W3f[131072];  // prepacked tf32 B-frags of kw3
__device__ __align__(8) unsigned g_W2f[8192];    // prepacked tf32 B-frags of kw2
__device__ unsigned g_CW1f[512];                 // prepacked fp16 B-frags of cw1 (phi mma)
__device__ float g_bh[NN * 32];                  // per-layer: B3-bias of m
__device__ float g_bt[NN * 32];                  // per-layer: bterm of phi
__device__ float g_acch[NN * 32];
__device__ float g_accc[NN * 3];
__device__ int   g_cntc[NN];
__device__ int   g_cntr[NN];
__device__ int   g_fill[NN];
__device__ int   g_cptr[NN + 1];
__device__ int   g_ebc[EE];

__device__ __forceinline__ unsigned f2tf32(float f) {
    unsigned u;
    asm("cvt.rna.tf32.f32 %0, %1;" : "=r"(u) : "f"(f));
    return u;
}
__device__ __forceinline__ void mma_tf32(float& c0, float& c1, float& c2, float& c3,
                                         unsigned a0, unsigned a1, unsigned a2, unsigned a3,
                                         unsigned b0, unsigned b1) {
    asm("mma.sync.aligned.m16n8k8.row.col.f32.tf32.tf32.f32 "
        "{%0,%1,%2,%3}, {%4,%5,%6,%7}, {%8,%9}, {%0,%1,%2,%3};"
        : "+f"(c0), "+f"(c1), "+f"(c2), "+f"(c3)
        : "r"(a0), "r"(a1), "r"(a2), "r"(a3), "r"(b0), "r"(b1));
}
__device__ __forceinline__ void mma_f16(float& c0, float& c1, float& c2, float& c3,
                                        unsigned a0, unsigned a1, unsigned a2, unsigned a3,
                                        unsigned b0, unsigned b1) {
    asm("mma.sync.aligned.m16n8k16.row.col.f32.f16.f16.f32 "
        "{%0,%1,%2,%3}, {%4,%5,%6,%7}, {%8,%9}, {%0,%1,%2,%3};"
        : "+f"(c0), "+f"(c1), "+f"(c2), "+f"(c3)
        : "r"(a0), "r"(a1), "r"(a2), "r"(a3), "r"(b0), "r"(b1));
}
__device__ __forceinline__ unsigned packh2(float a, float b) {
    __half2 h = __floats2half2_rn(a, b);
    return *(unsigned*)&h;
}
__device__ __forceinline__ void ldmat4(unsigned& r0, unsigned& r1, unsigned& r2, unsigned& r3,
                                       unsigned addr) {
    asm volatile("ldmatrix.sync.aligned.m8n8.x4.shared.b16 {%0,%1,%2,%3}, [%4];"
        : "=r"(r0), "=r"(r1), "=r"(r2), "=r"(r3) : "r"(addr));
}

// ---------------- prepack W3/W2/CW1 fragments + zero counters (once) --------------
__global__ void k_pack(const float* __restrict__ W3, const float* __restrict__ W2,
                       const float* __restrict__ CW1) {
    int tid = blockIdx.x * 256 + threadIdx.x;
    if (tid < 131072) {
        int b01 = tid & 1, lane = (tid >> 1) & 31, ks = (tid >> 6) & 3;
        int fo = (tid >> 8) & 31, cg = tid >> 13;
        int qr = lane >> 2, qc = lane & 3;
        g_W3f[tid] = f2tf32(W3[(size_t)(cg * 256 + fo * 8 + qr) * 32 + ks * 8 + qc + b01 * 4]);
    }
    if (tid < 8192) {
        int b01 = tid & 1, lane = (tid >> 1) & 31, ks = (tid >> 6) & 3;
        int fo = (tid >> 8) & 15, half = tid >> 12;
        int qr = lane >> 2, qc = lane & 3;
        g_W2f[tid] = f2tf32(W2[(half * 32 + ks * 8 + qc + b01 * 4) * 128 + fo * 8 + qr]);
    }
    if (tid < 512) {
        int lane = tid & 31, f = tid >> 5;
        int b01 = f & 1, nt = (f >> 1) & 3, ks2 = f >> 3;
        int qr = lane >> 2, qc = lane & 3;
        int j0 = ks2 * 16 + 2 * qc + b01 * 8, i = nt * 8 + qr;
        g_CW1f[f * 32 + lane] = packh2(CW1[j0 * 32 + i], CW1[(j0 + 1) * 32 + i]);
    }
    if (tid < NN) { g_cntc[tid] = 0; g_cntr[tid] = 0; g_fill[tid] = 0; }
}

// ---------------- init: h = x@fc1+b, coord copy, zero acc, edge histogram ---------
__global__ void k_prep(const float* __restrict__ x, const float* __restrict__ w,
                       const float* __restrict__ b, const float* __restrict__ ci,
                       const int* __restrict__ ei) {
    int idx = blockIdx.x * blockDim.x + threadIdx.x;
    if (idx < NN * 32) {
        int n = idx >> 5, j = idx & 31;
        float s = b[j];
        s += x[n * 3 + 0] * w[j] + x[n * 3 + 1] * w[32 + j] + x[n * 3 + 2] * w[64 + j];
        g_h[idx] = s;
        g_acch[idx] = 0.f;
    }
    if (idx < NN * 3) { g_coord[idx] = ci[idx]; g_accc[idx] = 0.f; }
    if (idx < EE) {
        atomicAdd(&g_cntr[ei[idx]], 1);
        atomicAdd(&g_cntc[ei[EE + idx]], 1);
    }
}

__global__ void k_scan() {
    __shared__ int ss[1024];
    int t = threadIdx.x;
    int base = t * 10;
    int loc[10];
    int s = 0;
#pragma unroll
    for (int i = 0; i < 10; i++) {
        int v = (base + i < NN) ? g_cntc[base + i] : 0;
        loc[i] = s; s += v;
    }
    ss[t] = s;
    __syncthreads();
    for (int off = 1; off < 1024; off <<= 1) {
        int v = (t >= off) ? ss[t - off] : 0;
        __syncthreads();
        ss[t] += v;
        __syncthreads();
    }
    int pre = (t > 0) ? ss[t - 1] : 0;
#pragma unroll
    for (int i = 0; i < 10; i++)
        if (base + i < NN) g_cptr[base + i] = pre + loc[i];
    if (t == 1023) g_cptr[NN] = ss[1023];
}

__global__ void k_scatter(const int* __restrict__ ei) {
    int e = blockIdx.x * blockDim.x + threadIdx.x;
    if (e < EE) {
        int c = ei[EE + e];
        int p = g_cptr[c] + atomicAdd(&g_fill[c], 1);
        g_ebc[p] = e;
    }
}

// ---------------- fused: edge-MLP | W3h GEMM (heterogeneous grid, 64 regs) --------
struct SmemEdge {
    unsigned k1[64][36];
    float kin[64][8];
    float w1[7 * 64];
    float b1[64];
    float b2[128];
};

__device__ __forceinline__ void edge_part(char* sb, int bid,
    const int* __restrict__ ei, const float* __restrict__ attr,
    const float* __restrict__ W1, const float* __restrict__ B1,
    const float* __restrict__ B2) {
    SmemEdge& sm = *(SmemEdge*)sb;
    int t = threadIdx.x, warp = t >> 5, lane = t & 31;
    int e0 = bid * 64;

    for (int i = t; i < 7 * 64; i += 256) sm.w1[i] = W1[i];
    if (t < 64) sm.b1[t] = B1[t];
    else if (t < 192) sm.b2[t - 64] = B2[t - 64];

    if (t < 64) {
        int e = e0 + t;
        float rad = 0.f;
        if (e < EE) {
            int r = ei[e], c = ei[EE + e];
            float d0 = g_coord[r * 3 + 0] - g_coord[c * 3 + 0];
            float d1 = g_coord[r * 3 + 1] - g_coord[c * 3 + 1];
            float d2 = g_coord[r * 3 + 2] - g_coord[c * 3 + 2];
            rad = d0 * d0 + d1 * d1 + d2 * d2;
#pragma unroll
            for (int q = 0; q < 6; q++) sm.kin[t][q] = attr[e * 6 + q];
        } else {
#pragma unroll
            for (int q = 0; q < 6; q++) sm.kin[t][q] = 0.f;
        }
        sm.kin[t][6] = rad;
        sm.kin[t][7] = 0.f;
    }
    __syncthreads();

    int wm = warp & 3, wn = warp >> 2;
    int qr = lane >> 2, qc = lane & 3;
    const uint2* bf = (const uint2*)g_W2f;
    float acc[8][4];
#pragma unroll
    for (int nt = 0; nt < 8; nt++)
#pragma unroll
        for (int j = 0; j < 4; j++) acc[nt][j] = 0.f;

    for (int half = 0; half < 2; half++) {
        for (int i = t; i < 64 * 32; i += 256) {
            int e = i >> 5, cc = i & 31, c = half * 32 + cc;
            float s = sm.b1[c];
#pragma unroll
            for (int q = 0; q < 7; q++) s = fmaf(sm.kin[e][q], sm.w1[q * 64 + c], s);
            sm.k1[e][cc] = f2tf32(fmaxf(s, 0.f));
        }
        __syncthreads();

#pragma unroll
        for (int ks = 0; ks < 4; ks++) {
            int k0 = ks * 8;
            unsigned a0 = sm.k1[wm * 16 + qr][k0 + qc];
            unsigned a1 = sm.k1[wm * 16 + qr + 8][k0 + qc];
            unsigned a2 = sm.k1[wm * 16 + qr][k0 + qc + 4];
            unsigned a3 = sm.k1[wm * 16 + qr + 8][k0 + qc + 4];
            uint2 bv[8];
#pragma unroll
            for (int nt = 0; nt < 8; nt++)
                bv[nt] = bf[((half * 16 + wn * 8 + nt) * 4 + ks) * 32 + lane];
#pragma unroll
            for (int nt = 0; nt < 8; nt++)
                mma_tf32(acc[nt][0], acc[nt][1], acc[nt][2], acc[nt][3],
                         a0, a1, a2, a3, bv[nt].x, bv[nt].y);
        }
        __syncthreads();
    }

    int eA = e0 + wm * 16 + qr, eB = eA + 8;
#pragma unroll
    for (int nt = 0; nt < 8; nt++) {
        int col = wn * 64 + nt * 8 + 2 * qc;
        float bx = sm.b2[col], by = sm.b2[col + 1];
        if (eA < EE)
            *(__half2*)&g_k2h[(size_t)eA * 128 + col] =
                __floats2half2_rn(fmaxf(acc[nt][0] + bx, 0.f), fmaxf(acc[nt][1] + by, 0.f));
        if (eB < EE)
            *(__half2*)&g_k2h[(size_t)eB * 128 + col] =
                __floats2half2_rn(fmaxf(acc[nt][2] + bx, 0.f), fmaxf(acc[nt][3] + by, 0.f));
    }
}

__device__ __forceinline__ void w3h_part(char* sb, int bid) {
    unsigned (*sa)[36] = (unsigned(*)[36])sb;
    int t = threadIdx.x, warp = t >> 5, lane = t & 31;
    int cg = bid & 15;
    int n0 = (bid >> 4) * 32;

    {
        int n = t >> 3, kq = t & 7;
        float4 v = make_float4(0.f, 0.f, 0.f, 0.f);
        if (n0 + n < NN) v = *(const float4*)&g_h[(n0 + n) * 32 + kq * 4];
        sa[n][kq * 4 + 0] = f2tf32(v.x); sa[n][kq * 4 + 1] = f2tf32(v.y);
        sa[n][kq * 4 + 2] = f2tf32(v.z); sa[n][kq * 4 + 3] = f2tf32(v.w);
    }
    __syncthreads();

    int wm = warp & 1, wn = warp >> 1;
    int qr = lane >> 2, qc = lane & 3;
    const uint2* bf = (const uint2*)g_W3f + (size_t)cg * 32 * 4 * 32;
    float acc[8][4];
#pragma unroll
    for (int nt = 0; nt < 8; nt++)
#pragma unroll
        for (int j = 0; j < 4; j++) acc[nt][j] = 0.f;

#pragma unroll
    for (int ks = 0; ks < 4; ks++) {
        int k0 = ks * 8;
        unsigned a0 = sa[wm * 16 + qr][k0 + qc];
        unsigned a1 = sa[wm * 16 + qr + 8][k0 + qc];
        unsigned a2 = sa[wm * 16 + qr][k0 + qc + 4];
        unsigned a3 = sa[wm * 16 + qr + 8][k0 + qc + 4];
        uint2 bv[8];
#pragma unroll
        for (int nt = 0; nt < 8; nt++)
            bv[nt] = bf[((wn * 8 + nt) * 4 + ks) * 32 + lane];
#pragma unroll
        for (int nt = 0; nt < 8; nt++)
            mma_tf32(acc[nt][0], acc[nt][1], acc[nt][2], acc[nt][3],
                     a0, a1, a2, a3, bv[nt].x, bv[nt].y);
    }
    __syncthreads();

    unsigned* so = (unsigned*)sb;
    int nlA = wm * 16 + qr, nlB = nlA + 8;
#pragma unroll
    for (int g = 0; g < 4; g++) {
#pragma unroll
        for (int j = 0; j < 2; j++) {
            int w = g * 32 + (2 * qc + j) * 4 + wn;
            __half2 vA = __floats2half2_rn(acc[g][j], acc[g + 4][j]);
            __half2 vB = __floats2half2_rn(acc[g][2 + j], acc[g + 4][2 + j]);
            so[nlA * 132 + w] = *(unsigned*)&vA;
            so[nlB * 132 + w] = *(unsigned*)&vB;
        }
    }
    __syncthreads();

    int ks = cg >> 1, par = cg & 1;
    for (int r = warp; r < 32; r += 8) {
        int n = n0 + r;
        if (n < NN) {
#pragma unroll
            for (int ch = 0; ch < 4; ch++)
                g_W3hB[(size_t)n * 2048 + ks * 256 + ch * 64 + par * 32 + lane] =
                    so[r * 132 + ch * 32 + lane];
        }
    }
}

__global__ __launch_bounds__(256) void k_fused(
    const int* __restrict__ ei, const float* __restrict__ attr,
    const float* __restrict__ W1, const float* __restrict__ B1,
    const float* __restrict__ B2) {
    constexpr unsigned SB = sizeof(SmemEdge) > 32 * 132 * 4u ? sizeof(SmemEdge) : 32 * 132 * 4u;
    __shared__ __align__(16) char sb[SB];
    if (blockIdx.x < EDGE_BLOCKS) edge_part(sb, blockIdx.x, ei, attr, W1, B1, B2);
    else                          w3h_part(sb, blockIdx.x - EDGE_BLOCKS);
}

// ---------------- bias GEMMs (standalone, layer 0): bh, bterm ---------------------
__global__ __launch_bounds__(256) void k_bias(
    const float* __restrict__ B3, const float* __restrict__ CW1,
    const float* __restrict__ CB1) {
    __shared__ float s_h[64][33];
    __shared__ float s_bh[64][33];
    __shared__ float s_w[32][33];
    __shared__ float s_cb[32];
    int t = threadIdx.x;
    int n0 = blockIdx.x * 64;
    for (int i = t; i < 2048; i += 256) {
        int nl = i >> 5, j = i & 31;
        s_h[nl][j] = (n0 + nl < NN) ? g_h[(n0 + nl) * 32 + j] : 0.f;
    }
    for (int i = t; i < 1024; i += 256) s_w[i & 31][i >> 5] = B3[i];
    if (t < 32) s_cb[t] = CB1[t];
    __syncthreads();

    float acc[8];
#pragma unroll
    for (int it = 0; it < 8; it++) {
        int item = t + 256 * it;
        int nl = item >> 5, i = item & 31;
        float a = 0.f;
#pragma unroll
        for (int j = 0; j < 32; j++) a = fmaf(s_w[j][i], s_h[nl][j], a);
        acc[it] = a;
    }
    __syncthreads();
#pragma unroll
    for (int it = 0; it < 8; it++) {
        int item = t + 256 * it;
        int nl = item >> 5, i = item & 31;
        s_bh[nl][i] = acc[it];
        int n = n0 + nl;
        if (n < NN) g_bh[n * 32 + i] = acc[it];
    }
    __syncthreads();
    for (int i = t; i < 1024; i += 256) s_w[i >> 5][i & 31] = CW1[i];
    __syncthreads();
#pragma unroll
    for (int it = 0; it < 8; it++) {
        int item = t + 256 * it;
        int nl = item >> 5, i = item & 31;
        float a = s_cb[i];
#pragma unroll
        for (int j = 0; j < 32; j++) a = fmaf(s_bh[nl][j], s_w[j][i], a);
        int n = n0 + nl;
        if (n < NN) g_bt[n * 32 + i] = a;
    }
}

// ---------------- update + next-layer bias fused (layers 0,1 tails) ---------------
__global__ __launch_bounds__(256) void k_updbias(
    const float* __restrict__ B3, const float* __restrict__ CW1,
    const float* __restrict__ CB1) {
    __shared__ float s_h[64][33];
    __shared__ float s_bh[64][33];
    __shared__ float s_w[32][33];
    __shared__ float s_cb[32];
    int t = threadIdx.x;
    int n0 = blockIdx.x * 64;
    // update h while staging
    for (int i = t; i < 2048; i += 256) {
        int nl = i >> 5, j = i & 31;
        int n = n0 + nl;
        float hn = 0.f;
        if (n < NN) {
            int c = g_cntr[n];
            float inv = 1.f / (float)(c > 0 ? c : 1);
            hn = fmaxf(g_h[n * 32 + j] + g_acch[n * 32 + j] * inv, 0.f);
            g_h[n * 32 + j] = hn;
            g_acch[n * 32 + j] = 0.f;
        }
        s_h[nl][j] = hn;
    }
    // coord update (64 nodes x 3)
    if (t < 192) {
        int n = n0 + t / 3, k = t % 3;
        if (n < NN) {
            int c = g_cntr[n];
            float inv = 1.f / (float)(c > 0 ? c : 1);
            g_coord[n * 3 + k] += g_accc[n * 3 + k] * inv;
            g_accc[n * 3 + k] = 0.f;
        }
    }
    for (int i = t; i < 1024; i += 256) s_w[i & 31][i >> 5] = B3[i];
    if (t < 32) s_cb[t] = CB1[t];
    __syncthreads();

    float acc[8];
#pragma unroll
    for (int it = 0; it < 8; it++) {
        int item = t + 256 * it;
        int nl = item >> 5, i = item & 31;
        float a = 0.f;
#pragma unroll
        for (int j = 0; j < 32; j++) a = fmaf(s_w[j][i], s_h[nl][j], a);
        acc[it] = a;
    }
    __syncthreads();
#pragma unroll
    for (int it = 0; it < 8; it++) {
        int item = t + 256 * it;
        int nl = item >> 5, i = item & 31;
        s_bh[nl][i] = acc[it];
        int n = n0 + nl;
        if (n < NN) g_bh[n * 32 + i] = acc[it];
    }
    __syncthreads();
    for (int i = t; i < 1024; i += 256) s_w[i >> 5][i & 31] = CW1[i];
    __syncthreads();
#pragma unroll
    for (int it = 0; it < 8; it++) {
        int item = t + 256 * it;
        int nl = item >> 5, i = item & 31;
        float a = s_cb[i];
#pragma unroll
        for (int j = 0; j < 32; j++) a = fmaf(s_bh[nl][j], s_w[j][i], a);
        int n = n0 + nl;
        if (n < NN) g_bt[n * 32 + i] = a;
    }
}

// -------- contraction: fp16 mma (ldmatrix A) for m AND phi ------------------------
__global__ __launch_bounds__(128) void k_contract_mma(
    const int* __restrict__ ei, const float* __restrict__ CW2) {
    __shared__ float  s_cw2[32];
    __shared__ __half s_a[4][16][136];
    __shared__ float  s_m[4][16][33];
    __shared__ float  s_p[4][16][33];
    __shared__ float  s_bt[4][32];
    __shared__ float  s_cc[4][4];
    __shared__ int    s_e[4][16];
    __shared__ int    s_rn[4][16];
    int t = threadIdx.x, lane = t & 31, w = t >> 5;
    if (t < 32) s_cw2[t] = CW2[t];
    __syncthreads();

    int n = blockIdx.x * 4 + w;
    if (n >= NN) return;
    int beg = g_cptr[n], end = g_cptr[n + 1];
    if (beg == end) return;

    int qr = lane >> 2, qc = lane & 3;

    unsigned u[64];
    const unsigned* bp = g_W3hB + (size_t)n * 2048 + lane;
#pragma unroll
    for (int f = 0; f < 64; f++) u[f] = bp[f * 32];

    unsigned ucwf[16];
#pragma unroll
    for (int f = 0; f < 16; f++) ucwf[f] = g_CW1f[f * 32 + lane];

    float bh = g_bh[n * 32 + lane];
    s_bt[w][lane] = g_bt[n * 32 + lane];
    if (lane < 3) s_cc[w][lane] = g_coord[n * 3 + lane];
    __syncwarp();

    // ldmatrix base address for A fragments
    int arow = lane & 15, acolh = (lane < 16) ? 0 : 8;
    unsigned abase = (unsigned)__cvta_generic_to_shared(&s_a[w][arow][acolh]);

    for (int g0 = beg; g0 < end; g0 += 16) {
        int gsz = min(16, end - g0);
        if (lane < 16) {
            int e = (lane < gsz) ? g_ebc[g0 + lane] : g_ebc[g0];
            s_e[w][lane] = e;
            s_rn[w][lane] = ei[e];
        }
        __syncwarp();
#pragma unroll
        for (int it = 0; it < 8; it++) {
            int idx = it * 32 + lane;
            int row = idx >> 4, part = idx & 15;
            ((uint4*)&s_a[w][row][0])[part] =
                ((const uint4*)(g_k2h + (size_t)s_e[w][row] * 128))[part];
        }
        __syncwarp();

        float acc[4][4];
#pragma unroll
        for (int nt = 0; nt < 4; nt++)
#pragma unroll
            for (int j = 0; j < 4; j++) acc[nt][j] = 0.f;

#pragma unroll
        for (int ks = 0; ks < 8; ks++) {
            unsigned a0, a1, a2, a3;
            ldmat4(a0, a1, a2, a3, abase + ks * 32);
#pragma unroll
            for (int nt = 0; nt < 4; nt++)
                mma_f16(acc[nt][0], acc[nt][1], acc[nt][2], acc[nt][3],
                        a0, a1, a2, a3, u[(ks * 4 + nt) * 2], u[(ks * 4 + nt) * 2 + 1]);
        }
        __syncwarp();
#pragma unroll
        for (int nt = 0; nt < 4; nt++) {
#pragma unroll
            for (int j = 0; j < 2; j++) {
                s_m[w][qr][nt * 8 + 2 * qc + j] = acc[nt][j];
                s_m[w][qr + 8][nt * 8 + 2 * qc + j] = acc[nt][2 + j];
            }
        }
        __syncwarp();

        float pacc[4][4];
#pragma unroll
        for (int nt = 0; nt < 4; nt++)
#pragma unroll
            for (int j = 0; j < 4; j++) pacc[nt][j] = 0.f;
#pragma unroll
        for (int ks2 = 0; ks2 < 2; ks2++) {
            int kb = ks2 * 16 + 2 * qc;
            unsigned a0 = packh2(s_m[w][qr][kb], s_m[w][qr][kb + 1]);
            unsigned a1 = packh2(s_m[w][qr + 8][kb], s_m[w][qr + 8][kb + 1]);
            unsigned a2 = packh2(s_m[w][qr][kb + 8], s_m[w][qr][kb + 9]);
            unsigned a3 = packh2(s_m[w][qr + 8][kb + 8], s_m[w][qr + 8][kb + 9]);
#pragma unroll
            for (int nt = 0; nt < 4; nt++)
                mma_f16(pacc[nt][0], pacc[nt][1], pacc[nt][2], pacc[nt][3],
                        a0, a1, a2, a3,
                        ucwf[(ks2 * 4 + nt) * 2], ucwf[(ks2 * 4 + nt) * 2 + 1]);
        }
#pragma unroll
        for (int nt = 0; nt < 4; nt++) {
#pragma unroll
            for (int j = 0; j < 2; j++) {
                s_p[w][qr][nt * 8 + 2 * qc + j] = pacc[nt][j];
                s_p[w][qr + 8][nt * 8 + 2 * qc + j] = pacc[nt][2 + j];
            }
        }
        __syncwarp();

        int rr = lane & 15;
        float tj = 0.f;
#pragma unroll
        for (int i = 0; i < 32; i++)
            tj = fmaf(fmaxf(s_p[w][rr][i] + s_bt[w][i], 0.f), s_cw2[i], tj);
        if (lane < gsz) {
            int rn = s_rn[w][lane];
#pragma unroll
            for (int k = 0; k < 3; k++)
                atomicAdd(&g_accc[rn * 3 + k],
                          (g_coord[rn * 3 + k] - s_cc[w][k]) * tj);
        }

        for (int r = 0; r < gsz; r++) {
            int rn = s_rn[w][r];
            float mi = s_m[w][r][lane] + bh;
            atomicAdd(&g_acch[rn * 32 + lane], mi);
        }
        __syncwarp();
    }
}

// ---------------- plain node update (layer 2 tail) --------------------------------
__global__ void k_update() {
    int idx = blockIdx.x * blockDim.x + threadIdx.x;
    if (idx >= NN * 32) return;
    int n = idx >> 5, j = idx & 31;
    int c = g_cntr[n];
    float inv = 1.f / (float)(c > 0 ? c : 1);
    g_h[idx] = fmaxf(g_h[idx] + g_acch[idx] * inv, 0.f);
    if (j < 3) g_coord[n * 3 + j] += g_accc[n * 3 + j] * inv;
}

// ---------------- final MLP + coord copy ------------------------------------------
__global__ void k_final(const float* __restrict__ w1, const float* __restrict__ b1,
                        const float* __restrict__ w2, const float* __restrict__ b2,
                        float* __restrict__ out) {
    int gid = blockIdx.x * blockDim.x + threadIdx.x;
    if (gid < NN * 3) out[NN + gid] = g_coord[gid];
    int lane = gid & 31;
    int n = gid >> 5;
    if (n >= NN) return;
    float hv = g_h[n * 32 + lane];
    float t0 = b1[lane], t1 = b1[32 + lane];
#pragma unroll
    for (int j = 0; j < 32; j++) {
        float hj = __shfl_sync(0xffffffffu, hv, j);
        t0 = fmaf(hj, w1[j * 64 + lane], t0);
        t1 = fmaf(hj, w1[j * 64 + 32 + lane], t1);
    }
    float s = fmaxf(t0, 0.f) * w2[lane] + fmaxf(t1, 0.f) * w2[32 + lane];
#pragma unroll
    for (int o = 16; o; o >>= 1) s += __shfl_xor_sync(0xffffffffu, s, o);
    if (lane == 0) out[n] = s + b2[0];
}

// ---------------------------------------------------------------------------------
extern "C" void kernel_launch(void* const* d_in, const int* in_sizes, int n_in,
                              void* d_out, int out_size) {
    const float* x    = (const float*)d_in[0];
    const int*   ei   = (const int*)d_in[1];
    const float* attr = (const float*)d_in[2];
    const float* ci   = (const float*)d_in[3];
    const float* f1w  = (const float*)d_in[4];
    const float* f1b  = (const float*)d_in[5];
    const float* kw1  = (const float*)d_in[6];
    const float* kb1  = (const float*)d_in[7];
    const float* kw2  = (const float*)d_in[8];
    const float* kb2  = (const float*)d_in[9];
    const float* kw3  = (const float*)d_in[10];
    const float* kb3  = (const float*)d_in[11];
    const float* cw1  = (const float*)d_in[12];
    const float* cb1  = (const float*)d_in[13];
    const float* cw2  = (const float*)d_in[14];
    const float* f2w1 = (const float*)d_in[15];
    const float* f2b1 = (const float*)d_in[16];
    const float* f2w2 = (const float*)d_in[17];
    const float* f2b2 = (const float*)d_in[18];
    float* out = (float*)d_out;

    int fused_grid = EDGE_BLOCKS + W3H_BLOCKS;

    k_pack<<<(131072 + 255) / 256, 256>>>(kw3, kw2, cw1);                    // 0
    k_prep<<<(NN * 32 + 255) / 256, 256>>>(x, f1w, f1b, ci, ei);             // 1
    k_scan<<<1, 1024>>>();                                                    // 2
    k_fused<<<fused_grid, 256>>>(ei, attr, kw1, kb1, kb2);                    // 3 <- profiled (L0)
    k_bias<<<BIAS_BLOCKS, 256>>>(kb3, cw1, cb1);                              // 4 (L0 bias)
    k_scatter<<<(EE + 255) / 256, 256>>>(ei);                                 // 5
    k_contract_mma<<<(NN + 3) / 4, 128>>>(ei, cw2);                           // 6 (L0)
    k_updbias<<<BIAS_BLOCKS, 256>>>(kb3, cw1, cb1);                           // 7 (L0 upd + L1 bias)

    // layer 1
    k_fused<<<fused_grid, 256>>>(ei, attr, kw1, kb1, kb2);
    k_contract_mma<<<(NN + 3) / 4, 128>>>(ei, cw2);
    k_updbias<<<BIAS_BLOCKS, 256>>>(kb3, cw1, cb1);                           // L1 upd + L2 bias

    // layer 2
    k_fused<<<fused_grid, 256>>>(ei, attr, kw1, kb1, kb2);
    k_contract_mma<<<(NN + 3) / 4, 128>>>(ei, cw2);
    k_update<<<(NN * 32 + 255) / 256, 256>>>();

    k_final<<<(NN * 32 + 255) / 256, 256>>>(f2w1, f2b1, f2w2, f2b2, out);
}

// round 16
// speedup vs baseline: 1.0042x; 1.0042x over previous
#include <cuda_runtime.h>
#include <cuda_fp16.h>

#define NN 10000
#define EE 100000
#define EDGE_BLOCKS ((EE + 63) / 64)
#define W3H_BLOCKS (((NN + 31) / 32) * 16)
#define BIAS_BLOCKS ((NN + 63) / 64)

// ---------------- scratch (static device globals; no allocation) ----------------
__device__ float g_h[NN * 32];
__device__ float g_coord[NN * 3];
__device__ __align__(16) __half g_k2h[(size_t)EE * 128];
__device__ unsigned g_W3hB[(size_t)NN * 2048];   // [n][frag:64][lane:32] half2 words
__device__ __align__(8) unsigned g_W3f[131072];  // prepacked tf32 B-frags of kw3
__device__ __align__(8) unsigned g_W2f[8192];    // prepacked tf32 B-frags of kw2
__device__ unsigned g_CW1f[512];                 // prepacked fp16 B-frags of cw1 (phi mma)
__device__ __align__(16) float g_kbase[(size_t)EDGE_BLOCKS * 64 * 64];  // attr@W1[:6]+b1
__device__ float g_bh[NN * 32];                  // per-layer: B3-bias of m
__device__ float g_bt[NN * 32];                  // per-layer: bterm of phi
__device__ float g_acch[NN * 32];
__device__ float g_accc[NN * 3];
__device__ int   g_cntc[NN];
__device__ int   g_cntr[NN];
__device__ int   g_fill[NN];
__device__ int   g_cptr[NN + 1];
__device__ int   g_ebc[EE];

__device__ __forceinline__ unsigned f2tf32(float f) {
    unsigned u;
    asm("cvt.rna.tf32.f32 %0, %1;" : "=r"(u) : "f"(f));
    return u;
}
__device__ __forceinline__ void mma_tf32(float& c0, float& c1, float& c2, float& c3,
                                         unsigned a0, unsigned a1, unsigned a2, unsigned a3,
                                         unsigned b0, unsigned b1) {
    asm("mma.sync.aligned.m16n8k8.row.col.f32.tf32.tf32.f32 "
        "{%0,%1,%2,%3}, {%4,%5,%6,%7}, {%8,%9}, {%0,%1,%2,%3};"
        : "+f"(c0), "+f"(c1), "+f"(c2), "+f"(c3)
        : "r"(a0), "r"(a1), "r"(a2), "r"(a3), "r"(b0), "r"(b1));
}
__device__ __forceinline__ void mma_f16(float& c0, float& c1, float& c2, float& c3,
                                        unsigned a0, unsigned a1, unsigned a2, unsigned a3,
                                        unsigned b0, unsigned b1) {
    asm("mma.sync.aligned.m16n8k16.row.col.f32.f16.f16.f32 "
        "{%0,%1,%2,%3}, {%4,%5,%6,%7}, {%8,%9}, {%0,%1,%2,%3};"
        : "+f"(c0), "+f"(c1), "+f"(c2), "+f"(c3)
        : "r"(a0), "r"(a1), "r"(a2), "r"(a3), "r"(b0), "r"(b1));
}
__device__ __forceinline__ unsigned packh2(float a, float b) {
    __half2 h = __floats2half2_rn(a, b);
    return *(unsigned*)&h;
}
__device__ __forceinline__ void ldmat4(unsigned& r0, unsigned& r1, unsigned& r2, unsigned& r3,
                                       unsigned addr) {
    asm volatile("ldmatrix.sync.aligned.m8n8.x4.shared.b16 {%0,%1,%2,%3}, [%4];"
        : "=r"(r0), "=r"(r1), "=r"(r2), "=r"(r3) : "r"(addr));
}

// ---------------- prepack W3/W2/CW1 fragments + zero counters (once) --------------
__global__ void k_pack(const float* __restrict__ W3, const float* __restrict__ W2,
                       const float* __restrict__ CW1) {
    int tid = blockIdx.x * 256 + threadIdx.x;
    if (tid < 131072) {
        int b01 = tid & 1, lane = (tid >> 1) & 31, ks = (tid >> 6) & 3;
        int fo = (tid >> 8) & 31, cg = tid >> 13;
        int qr = lane >> 2, qc = lane & 3;
        g_W3f[tid] = f2tf32(W3[(size_t)(cg * 256 + fo * 8 + qr) * 32 + ks * 8 + qc + b01 * 4]);
    }
    if (tid < 8192) {
        int b01 = tid & 1, lane = (tid >> 1) & 31, ks = (tid >> 6) & 3;
        int fo = (tid >> 8) & 15, half = tid >> 12;
        int qr = lane >> 2, qc = lane & 3;
        g_W2f[tid] = f2tf32(W2[(half * 32 + ks * 8 + qc + b01 * 4) * 128 + fo * 8 + qr]);
    }
    if (tid < 512) {
        int lane = tid & 31, f = tid >> 5;
        int b01 = f & 1, nt = (f >> 1) & 3, ks2 = f >> 3;
        int qr = lane >> 2, qc = lane & 3;
        int j0 = ks2 * 16 + 2 * qc + b01 * 8, i = nt * 8 + qr;
        g_CW1f[f * 32 + lane] = packh2(CW1[j0 * 32 + i], CW1[(j0 + 1) * 32 + i]);
    }
    if (tid < NN) { g_cntc[tid] = 0; g_cntr[tid] = 0; g_fill[tid] = 0; }
}

// ---------------- kbase: base[e][c] = b1[c] + sum_{q<6} attr[e,q]*W1[q,c] (once) ---
__global__ __launch_bounds__(256) void k_base(
    const float* __restrict__ attr, const float* __restrict__ W1,
    const float* __restrict__ B1) {
    __shared__ float s_attr[64][6];
    __shared__ float s_w1[6 * 64];
    __shared__ float s_b1[64];
    int t = threadIdx.x;
    int e0 = blockIdx.x * 64;
    for (int i = t; i < 6 * 64; i += 256) s_w1[i] = W1[i];
    if (t < 64) s_b1[t] = B1[t];
    // stage attr rows (block needs attr[e0*6 .. e0*6+384))
    for (int i = t; i < 96; i += 256) {
        float4 v = make_float4(0.f, 0.f, 0.f, 0.f);
        if (e0 * 6 + i * 4 + 3 < EE * 6) v = *(const float4*)&attr[e0 * 6 + i * 4];
        else {
            for (int j = 0; j < 4; j++) {
                int idx = e0 * 6 + i * 4 + j;
                ((float*)&v)[j] = (idx < EE * 6) ? attr[idx] : 0.f;
            }
        }
        ((float4*)s_attr)[i] = v;
    }
    __syncthreads();

    int ey = t >> 2, cq = t & 3;   // edge ey, cols cq*16..+15
    float a[6];
#pragma unroll
    for (int q = 0; q < 6; q++) a[q] = (e0 + ey < EE) ? s_attr[ey][q] : 0.f;
#pragma unroll
    for (int i4 = 0; i4 < 4; i4++) {
        float4 r;
#pragma unroll
        for (int j = 0; j < 4; j++) {
            int c = cq * 16 + i4 * 4 + j;
            float s = s_b1[c];
#pragma unroll
            for (int q = 0; q < 6; q++) s = fmaf(a[q], s_w1[q * 64 + c], s);
            ((float*)&r)[j] = s;
        }
        *(float4*)&g_kbase[(size_t)(e0 + ey) * 64 + cq * 16 + i4 * 4] = r;
    }
}

// ---------------- init: h = x@fc1+b, coord copy, zero acc, edge histogram ---------
__global__ void k_prep(const float* __restrict__ x, const float* __restrict__ w,
                       const float* __restrict__ b, const float* __restrict__ ci,
                       const int* __restrict__ ei) {
    int idx = blockIdx.x * blockDim.x + threadIdx.x;
    if (idx < NN * 32) {
        int n = idx >> 5, j = idx & 31;
        float s = b[j];
        s += x[n * 3 + 0] * w[j] + x[n * 3 + 1] * w[32 + j] + x[n * 3 + 2] * w[64 + j];
        g_h[idx] = s;
        g_acch[idx] = 0.f;
    }
    if (idx < NN * 3) { g_coord[idx] = ci[idx]; g_accc[idx] = 0.f; }
    if (idx < EE) {
        atomicAdd(&g_cntr[ei[idx]], 1);
        atomicAdd(&g_cntc[ei[EE + idx]], 1);
    }
}

__global__ void k_scan() {
    __shared__ int ss[1024];
    int t = threadIdx.x;
    int base = t * 10;
    int loc[10];
    int s = 0;
#pragma unroll
    for (int i = 0; i < 10; i++) {
        int v = (base + i < NN) ? g_cntc[base + i] : 0;
        loc[i] = s; s += v;
    }
    ss[t] = s;
    __syncthreads();
    for (int off = 1; off < 1024; off <<= 1) {
        int v = (t >= off) ? ss[t - off] : 0;
        __syncthreads();
        ss[t] += v;
        __syncthreads();
    }
    int pre = (t > 0) ? ss[t - 1] : 0;
#pragma unroll
    for (int i = 0; i < 10; i++)
        if (base + i < NN) g_cptr[base + i] = pre + loc[i];
    if (t == 1023) g_cptr[NN] = ss[1023];
}

__global__ void k_scatter(const int* __restrict__ ei) {
    int e = blockIdx.x * blockDim.x + threadIdx.x;
    if (e < EE) {
        int c = ei[EE + e];
        int p = g_cptr[c] + atomicAdd(&g_fill[c], 1);
        g_ebc[p] = e;
    }
}

// ---------------- fused: edge-MLP | W3h GEMM (heterogeneous grid) -----------------
struct SmemEdge {
    unsigned k1[64][36];
    float rad[64];
    float w1r[64];
    float b2[128];
};

__device__ __forceinline__ void edge_part(char* sb, int bid,
    const int* __restrict__ ei, const float* __restrict__ W1,
    const float* __restrict__ B2) {
    SmemEdge& sm = *(SmemEdge*)sb;
    int t = threadIdx.x, warp = t >> 5, lane = t & 31;
    int e0 = bid * 64;

    if (t < 64) {
        int e = e0 + t;
        float rad = 0.f;
        if (e < EE) {
            int r = ei[e], c = ei[EE + e];
            float d0 = g_coord[r * 3 + 0] - g_coord[c * 3 + 0];
            float d1 = g_coord[r * 3 + 1] - g_coord[c * 3 + 1];
            float d2 = g_coord[r * 3 + 2] - g_coord[c * 3 + 2];
            rad = d0 * d0 + d1 * d1 + d2 * d2;
        }
        sm.rad[t] = rad;
    } else if (t < 128) {
        sm.w1r[t - 64] = W1[6 * 64 + (t - 64)];
    } else {
        sm.b2[t - 128] = B2[t - 128];
    }
    __syncthreads();

    int wm = warp & 3, wn = warp >> 2;
    int qr = lane >> 2, qc = lane & 3;
    const uint2* bf = (const uint2*)g_W2f;
    float acc[8][4];
#pragma unroll
    for (int nt = 0; nt < 8; nt++)
#pragma unroll
        for (int j = 0; j < 4; j++) acc[nt][j] = 0.f;

    for (int half = 0; half < 2; half++) {
        // phase 1: k1 = relu(base + rad * w1row6), tf32
#pragma unroll
        for (int it = 0; it < 2; it++) {
            int i = t + 256 * it;
            int eloc = i >> 3, cq = i & 7;
            int c = half * 32 + cq * 4;
            float4 b4 = *(const float4*)&g_kbase[(size_t)(e0 + eloc) * 64 + c];
            float4 w4 = *(const float4*)&sm.w1r[c];
            float rad = sm.rad[eloc];
            sm.k1[eloc][cq * 4 + 0] = f2tf32(fmaxf(fmaf(rad, w4.x, b4.x), 0.f));
            sm.k1[eloc][cq * 4 + 1] = f2tf32(fmaxf(fmaf(rad, w4.y, b4.y), 0.f));
            sm.k1[eloc][cq * 4 + 2] = f2tf32(fmaxf(fmaf(rad, w4.z, b4.z), 0.f));
            sm.k1[eloc][cq * 4 + 3] = f2tf32(fmaxf(fmaf(rad, w4.w, b4.w), 0.f));
        }
        __syncthreads();

#pragma unroll
        for (int ks = 0; ks < 4; ks++) {
            int k0 = ks * 8;
            unsigned a0 = sm.k1[wm * 16 + qr][k0 + qc];
            unsigned a1 = sm.k1[wm * 16 + qr + 8][k0 + qc];
            unsigned a2 = sm.k1[wm * 16 + qr][k0 + qc + 4];
            unsigned a3 = sm.k1[wm * 16 + qr + 8][k0 + qc + 4];
            uint2 bv[8];
#pragma unroll
            for (int nt = 0; nt < 8; nt++)
                bv[nt] = bf[((half * 16 + wn * 8 + nt) * 4 + ks) * 32 + lane];
#pragma unroll
            for (int nt = 0; nt < 8; nt++)
                mma_tf32(acc[nt][0], acc[nt][1], acc[nt][2], acc[nt][3],
                         a0, a1, a2, a3, bv[nt].x, bv[nt].y);
        }
        __syncthreads();
    }

    int eA = e0 + wm * 16 + qr, eB = eA + 8;
#pragma unroll
    for (int nt = 0; nt < 8; nt++) {
        int col = wn * 64 + nt * 8 + 2 * qc;
        float bx = sm.b2[col], by = sm.b2[col + 1];
        if (eA < EE)
            *(__half2*)&g_k2h[(size_t)eA * 128 + col] =
                __floats2half2_rn(fmaxf(acc[nt][0] + bx, 0.f), fmaxf(acc[nt][1] + by, 0.f));
        if (eB < EE)
            *(__half2*)&g_k2h[(size_t)eB * 128 + col] =
                __floats2half2_rn(fmaxf(acc[nt][2] + bx, 0.f), fmaxf(acc[nt][3] + by, 0.f));
    }
}

__device__ __forceinline__ void w3h_part(char* sb, int bid) {
    unsigned (*sa)[36] = (unsigned(*)[36])sb;
    int t = threadIdx.x, warp = t >> 5, lane = t & 31;
    int cg = bid & 15;
    int n0 = (bid >> 4) * 32;

    {
        int n = t >> 3, kq = t & 7;
        float4 v = make_float4(0.f, 0.f, 0.f, 0.f);
        if (n0 + n < NN) v = *(const float4*)&g_h[(n0 + n) * 32 + kq * 4];
        sa[n][kq * 4 + 0] = f2tf32(v.x); sa[n][kq * 4 + 1] = f2tf32(v.y);
        sa[n][kq * 4 + 2] = f2tf32(v.z); sa[n][kq * 4 + 3] = f2tf32(v.w);
    }
    __syncthreads();

    int wm = warp & 1, wn = warp >> 1;
    int qr = lane >> 2, qc = lane & 3;
    const uint2* bf = (const uint2*)g_W3f + (size_t)cg * 32 * 4 * 32;
    float acc[8][4];
#pragma unroll
    for (int nt = 0; nt < 8; nt++)
#pragma unroll
        for (int j = 0; j < 4; j++) acc[nt][j] = 0.f;

#pragma unroll
    for (int ks = 0; ks < 4; ks++) {
        int k0 = ks * 8;
        unsigned a0 = sa[wm * 16 + qr][k0 + qc];
        unsigned a1 = sa[wm * 16 + qr + 8][k0 + qc];
        unsigned a2 = sa[wm * 16 + qr][k0 + qc + 4];
        unsigned a3 = sa[wm * 16 + qr + 8][k0 + qc + 4];
        uint2 bv[8];
#pragma unroll
        for (int nt = 0; nt < 8; nt++)
            bv[nt] = bf[((wn * 8 + nt) * 4 + ks) * 32 + lane];
#pragma unroll
        for (int nt = 0; nt < 8; nt++)
            mma_tf32(acc[nt][0], acc[nt][1], acc[nt][2], acc[nt][3],
                     a0, a1, a2, a3, bv[nt].x, bv[nt].y);
    }
    __syncthreads();

    unsigned* so = (unsigned*)sb;
    int nlA = wm * 16 + qr, nlB = nlA + 8;
#pragma unroll
    for (int g = 0; g < 4; g++) {
#pragma unroll
        for (int j = 0; j < 2; j++) {
            int w = g * 32 + (2 * qc + j) * 4 + wn;
            __half2 vA = __floats2half2_rn(acc[g][j], acc[g + 4][j]);
            __half2 vB = __floats2half2_rn(acc[g][2 + j], acc[g + 4][2 + j]);
            so[nlA * 132 + w] = *(unsigned*)&vA;
            so[nlB * 132 + w] = *(unsigned*)&vB;
        }
    }
    __syncthreads();

    int ks = cg >> 1, par = cg & 1;
    for (int r = warp; r < 32; r += 8) {
        int n = n0 + r;
        if (n < NN) {
#pragma unroll
            for (int ch = 0; ch < 4; ch++)
                g_W3hB[(size_t)n * 2048 + ks * 256 + ch * 64 + par * 32 + lane] =
                    so[r * 132 + ch * 32 + lane];
        }
    }
}

__global__ __launch_bounds__(256) void k_fused(
    const int* __restrict__ ei, const float* __restrict__ W1,
    const float* __restrict__ B2) {
    constexpr unsigned SB = sizeof(SmemEdge) > 32 * 132 * 4u ? sizeof(SmemEdge) : 32 * 132 * 4u;
    __shared__ __align__(16) char sb[SB];
    if (blockIdx.x < EDGE_BLOCKS) edge_part(sb, blockIdx.x, ei, W1, B2);
    else                          w3h_part(sb, blockIdx.x - EDGE_BLOCKS);
}

// ---------------- bias GEMMs (standalone, layer 0): bh, bterm ---------------------
__global__ __launch_bounds__(256) void k_bias(
    const float* __restrict__ B3, const float* __restrict__ CW1,
    const float* __restrict__ CB1) {
    __shared__ float s_h[64][33];
    __shared__ float s_bh[64][33];
    __shared__ float s_w[32][33];
    __shared__ float s_cb[32];
    int t = threadIdx.x;
    int n0 = blockIdx.x * 64;
    for (int i = t; i < 2048; i += 256) {
        int nl = i >> 5, j = i & 31;
        s_h[nl][j] = (n0 + nl < NN) ? g_h[(n0 + nl) * 32 + j] : 0.f;
    }
    for (int i = t; i < 1024; i += 256) s_w[i & 31][i >> 5] = B3[i];
    if (t < 32) s_cb[t] = CB1[t];
    __syncthreads();

    float acc[8];
#pragma unroll
    for (int it = 0; it < 8; it++) {
        int item = t + 256 * it;
        int nl = item >> 5, i = item & 31;
        float a = 0.f;
#pragma unroll
        for (int j = 0; j < 32; j++) a = fmaf(s_w[j][i], s_h[nl][j], a);
        acc[it] = a;
    }
    __syncthreads();
#pragma unroll
    for (int it = 0; it < 8; it++) {
        int item = t + 256 * it;
        int nl = item >> 5, i = item & 31;
        s_bh[nl][i] = acc[it];
        int n = n0 + nl;
        if (n < NN) g_bh[n * 32 + i] = acc[it];
    }
    __syncthreads();
    for (int i = t; i < 1024; i += 256) s_w[i >> 5][i & 31] = CW1[i];
    __syncthreads();
#pragma unroll
    for (int it = 0; it < 8; it++) {
        int item = t + 256 * it;
        int nl = item >> 5, i = item & 31;
        float a = s_cb[i];
#pragma unroll
        for (int j = 0; j < 32; j++) a = fmaf(s_bh[nl][j], s_w[j][i], a);
        int n = n0 + nl;
        if (n < NN) g_bt[n * 32 + i] = a;
    }
}

// ---------------- update + next-layer bias fused (layers 0,1 tails) ---------------
__global__ __launch_bounds__(256) void k_updbias(
    const float* __restrict__ B3, const float* __restrict__ CW1,
    const float* __restrict__ CB1) {
    __shared__ float s_h[64][33];
    __shared__ float s_bh[64][33];
    __shared__ float s_w[32][33];
    __shared__ float s_cb[32];
    int t = threadIdx.x;
    int n0 = blockIdx.x * 64;
    for (int i = t; i < 2048; i += 256) {
        int nl = i >> 5, j = i & 31;
        int n = n0 + nl;
        float hn = 0.f;
        if (n < NN) {
            int c = g_cntr[n];
            float inv = 1.f / (float)(c > 0 ? c : 1);
            hn = fmaxf(g_h[n * 32 + j] + g_acch[n * 32 + j] * inv, 0.f);
            g_h[n * 32 + j] = hn;
            g_acch[n * 32 + j] = 0.f;
        }
        s_h[nl][j] = hn;
    }
    if (t < 192) {
        int n = n0 + t / 3, k = t % 3;
        if (n < NN) {
            int c = g_cntr[n];
            float inv = 1.f / (float)(c > 0 ? c : 1);
            g_coord[n * 3 + k] += g_accc[n * 3 + k] * inv;
            g_accc[n * 3 + k] = 0.f;
        }
    }
    for (int i = t; i < 1024; i += 256) s_w[i & 31][i >> 5] = B3[i];
    if (t < 32) s_cb[t] = CB1[t];
    __syncthreads();

    float acc[8];
#pragma unroll
    for (int it = 0; it < 8; it++) {
        int item = t + 256 * it;
        int nl = item >> 5, i = item & 31;
        float a = 0.f;
#pragma unroll
        for (int j = 0; j < 32; j++) a = fmaf(s_w[j][i], s_h[nl][j], a);
        acc[it] = a;
    }
    __syncthreads();
#pragma unroll
    for (int it = 0; it < 8; it++) {
        int item = t + 256 * it;
        int nl = item >> 5, i = item & 31;
        s_bh[nl][i] = acc[it];
        int n = n0 + nl;
        if (n < NN) g_bh[n * 32 + i] = acc[it];
    }
    __syncthreads();
    for (int i = t; i < 1024; i += 256) s_w[i >> 5][i & 31] = CW1[i];
    __syncthreads();
#pragma unroll
    for (int it = 0; it < 8; it++) {
        int item = t + 256 * it;
        int nl = item >> 5, i = item & 31;
        float a = s_cb[i];
#pragma unroll
        for (int j = 0; j < 32; j++) a = fmaf(s_bh[nl][j], s_w[j][i], a);
        int n = n0 + nl;
        if (n < NN) g_bt[n * 32 + i] = a;
    }
}

// -------- contraction: fp16 mma (ldmatrix A) for m AND phi ------------------------
__global__ __launch_bounds__(128) void k_contract_mma(
    const int* __restrict__ ei, const float* __restrict__ CW2) {
    __shared__ float  s_cw2[32];
    __shared__ __half s_a[4][16][136];
    __shared__ float  s_m[4][16][33];
    __shared__ float  s_p[4][16][33];
    __shared__ float  s_bt[4][32];
    __shared__ float  s_cc[4][4];
    __shared__ int    s_e[4][16];
    __shared__ int    s_rn[4][16];
    int t = threadIdx.x, lane = t & 31, w = t >> 5;
    if (t < 32) s_cw2[t] = CW2[t];
    __syncthreads();

    int n = blockIdx.x * 4 + w;
    if (n >= NN) return;
    int beg = g_cptr[n], end = g_cptr[n + 1];
    if (beg == end) return;

    int qr = lane >> 2, qc = lane & 3;

    unsigned u[64];
    const unsigned* bp = g_W3hB + (size_t)n * 2048 + lane;
#pragma unroll
    for (int f = 0; f < 64; f++) u[f] = bp[f * 32];

    unsigned ucwf[16];
#pragma unroll
    for (int f = 0; f < 16; f++) ucwf[f] = g_CW1f[f * 32 + lane];

    float bh = g_bh[n * 32 + lane];
    s_bt[w][lane] = g_bt[n * 32 + lane];
    if (lane < 3) s_cc[w][lane] = g_coord[n * 3 + lane];
    __syncwarp();

    int arow = lane & 15, acolh = (lane < 16) ? 0 : 8;
    unsigned abase = (unsigned)__cvta_generic_to_shared(&s_a[w][arow][acolh]);

    for (int g0 = beg; g0 < end; g0 += 16) {
        int gsz = min(16, end - g0);
        if (lane < 16) {
            int e = (lane < gsz) ? g_ebc[g0 + lane] : g_ebc[g0];
            s_e[w][lane] = e;
            s_rn[w][lane] = ei[e];
        }
        __syncwarp();
#pragma unroll
        for (int it = 0; it < 8; it++) {
            int idx = it * 32 + lane;
            int row = idx >> 4, part = idx & 15;
            ((uint4*)&s_a[w][row][0])[part] =
                ((const uint4*)(g_k2h + (size_t)s_e[w][row] * 128))[part];
        }
        __syncwarp();

        float acc[4][4];
#pragma unroll
        for (int nt = 0; nt < 4; nt++)
#pragma unroll
            for (int j = 0; j < 4; j++) acc[nt][j] = 0.f;

#pragma unroll
        for (int ks = 0; ks < 8; ks++) {
            unsigned a0, a1, a2, a3;
            ldmat4(a0, a1, a2, a3, abase + ks * 32);
#pragma unroll
            for (int nt = 0; nt < 4; nt++)
                mma_f16(acc[nt][0], acc[nt][1], acc[nt][2], acc[nt][3],
                        a0, a1, a2, a3, u[(ks * 4 + nt) * 2], u[(ks * 4 + nt) * 2 + 1]);
        }
        __syncwarp();
#pragma unroll
        for (int nt = 0; nt < 4; nt++) {
#pragma unroll
            for (int j = 0; j < 2; j++) {
                s_m[w][qr][nt * 8 + 2 * qc + j] = acc[nt][j];
                s_m[w][qr + 8][nt * 8 + 2 * qc + j] = acc[nt][2 + j];
            }
        }
        __syncwarp();

        float pacc[4][4];
#pragma unroll
        for (int nt = 0; nt < 4; nt++)
#pragma unroll
            for (int j = 0; j < 4; j++) pacc[nt][j] = 0.f;
#pragma unroll
        for (int ks2 = 0; ks2 < 2; ks2++) {
            int kb = ks2 * 16 + 2 * qc;
            unsigned a0 = packh2(s_m[w][qr][kb], s_m[w][qr][kb + 1]);
            unsigned a1 = packh2(s_m[w][qr + 8][kb], s_m[w][qr + 8][kb + 1]);
            unsigned a2 = packh2(s_m[w][qr][kb + 8], s_m[w][qr][kb + 9]);
            unsigned a3 = packh2(s_m[w][qr + 8][kb + 8], s_m[w][qr + 8][kb + 9]);
#pragma unroll
            for (int nt = 0; nt < 4; nt++)
                mma_f16(pacc[nt][0], pacc[nt][1], pacc[nt][2], pacc[nt][3],
                        a0, a1, a2, a3,
                        ucwf[(ks2 * 4 + nt) * 2], ucwf[(ks2 * 4 + nt) * 2 + 1]);
        }
#pragma unroll
        for (int nt = 0; nt < 4; nt++) {
#pragma unroll
            for (int j = 0; j < 2; j++) {
                s_p[w][qr][nt * 8 + 2 * qc + j] = pacc[nt][j];
                s_p[w][qr + 8][nt * 8 + 2 * qc + j] = pacc[nt][2 + j];
            }
        }
        __syncwarp();

        int rr = lane & 15;
        float tj = 0.f;
#pragma unroll
        for (int i = 0; i < 32; i++)
            tj = fmaf(fmaxf(s_p[w][rr][i] + s_bt[w][i], 0.f), s_cw2[i], tj);
        if (lane < gsz) {
            int rn = s_rn[w][lane];
#pragma unroll
            for (int k = 0; k < 3; k++)
                atomicAdd(&g_accc[rn * 3 + k],
                          (g_coord[rn * 3 + k] - s_cc[w][k]) * tj);
        }

        for (int r = 0; r < gsz; r++) {
            int rn = s_rn[w][r];
            float mi = s_m[w][r][lane] + bh;
            atomicAdd(&g_acch[rn * 32 + lane], mi);
        }
        __syncwarp();
    }
}

// ---------------- plain node update (layer 2 tail) --------------------------------
__global__ void k_update() {
    int idx = blockIdx.x * blockDim.x + threadIdx.x;
    if (idx >= NN * 32) return;
    int n = idx >> 5, j = idx & 31;
    int c = g_cntr[n];
    float inv = 1.f / (float)(c > 0 ? c : 1);
    g_h[idx] = fmaxf(g_h[idx] + g_acch[idx] * inv, 0.f);
    if (j < 3) g_coord[n * 3 + j] += g_accc[n * 3 + j] * inv;
}

// ---------------- final MLP + coord copy ------------------------------------------
__global__ void k_final(const float* __restrict__ w1, const float* __restrict__ b1,
                        const float* __restrict__ w2, const float* __restrict__ b2,
                        float* __restrict__ out) {
    int gid = blockIdx.x * blockDim.x + threadIdx.x;
    if (gid < NN * 3) out[NN + gid] = g_coord[gid];
    int lane = gid & 31;
    int n = gid >> 5;
    if (n >= NN) return;
    float hv = g_h[n * 32 + lane];
    float t0 = b1[lane], t1 = b1[32 + lane];
#pragma unroll
    for (int j = 0; j < 32; j++) {
        float hj = __shfl_sync(0xffffffffu, hv, j);
        t0 = fmaf(hj, w1[j * 64 + lane], t0);
        t1 = fmaf(hj, w1[j * 64 + 32 + lane], t1);
    }
    float s = fmaxf(t0, 0.f) * w2[lane] + fmaxf(t1, 0.f) * w2[32 + lane];
#pragma unroll
    for (int o = 16; o; o >>= 1) s += __shfl_xor_sync(0xffffffffu, s, o);
    if (lane == 0) out[n] = s + b2[0];
}

// ---------------------------------------------------------------------------------
extern "C" void kernel_launch(void* const* d_in, const int* in_sizes, int n_in,
                              void* d_out, int out_size) {
    const float* x    = (const float*)d_in[0];
    const int*   ei   = (const int*)d_in[1];
    const float* attr = (const float*)d_in[2];
    const float* ci   = (const float*)d_in[3];
    const float* f1w  = (const float*)d_in[4];
    const float* f1b  = (const float*)d_in[5];
    const float* kw1  = (const float*)d_in[6];
    const float* kb1  = (const float*)d_in[7];
    const float* kw2  = (const float*)d_in[8];
    const float* kb2  = (const float*)d_in[9];
    const float* kw3  = (const float*)d_in[10];
    const float* kb3  = (const float*)d_in[11];
    const float* cw1  = (const float*)d_in[12];
    const float* cb1  = (const float*)d_in[13];
    const float* cw2  = (const float*)d_in[14];
    const float* f2w1 = (const float*)d_in[15];
    const float* f2b1 = (const float*)d_in[16];
    const float* f2w2 = (const float*)d_in[17];
    const float* f2b2 = (const float*)d_in[18];
    float* out = (float*)d_out;

    int fused_grid = EDGE_BLOCKS + W3H_BLOCKS;

    k_pack<<<(131072 + 255) / 256, 256>>>(kw3, kw2, cw1);                    // 0
    k_prep<<<(NN * 32 + 255) / 256, 256>>>(x, f1w, f1b, ci, ei);             // 1
    k_base<<<EDGE_BLOCKS, 256>>>(attr, kw1, kb1);                            // 2
    k_fused<<<fused_grid, 256>>>(ei, kw1, kb2);                              // 3 <- profiled (L0)
    k_scan<<<1, 1024>>>();                                                    // 4
    k_bias<<<BIAS_BLOCKS, 256>>>(kb3, cw1, cb1);                              // 5 (L0 bias)
    k_scatter<<<(EE + 255) / 256, 256>>>(ei);                                 // 6
    k_contract_mma<<<(NN + 3) / 4, 128>>>(ei, cw2);                           // 7 (L0)
    k_updbias<<<BIAS_BLOCKS, 256>>>(kb3, cw1, cb1);                           // 8 (L0 upd + L1 bias)

    // layer 1
    k_fused<<<fused_grid, 256>>>(ei, kw1, kb2);
    k_contract_mma<<<(NN + 3) / 4, 128>>>(ei, cw2);
    k_updbias<<<BIAS_BLOCKS, 256>>>(kb3, cw1, cb1);                           // L1 upd + L2 bias

    // layer 2
    k_fused<<<fused_grid, 256>>>(ei, kw1, kb2);
    k_contract_mma<<<(NN + 3) / 4, 128>>>(ei, cw2);
    k_update<<<(NN * 32 + 255) / 256, 256>>>();

    k_final<<<(NN * 32 + 255) / 256, 256>>>(f2w1, f2b1, f2w2, f2b2, out);
}